// round 16
// baseline (speedup 1.0000x reference)
#include <cuda_runtime.h>
#include <math.h>

#define E_    256000
#define NN_   16000
#define M_    32
#define LAT_  128
#define IN2B_ 136
#define HID_  256
#define GENW_ 160
#define TILE  16
#define TPB   128

// ---------------- scratch (static device globals; no allocation) ----------------
static __device__ float    d_eq     [(size_t)E_ * M_ * 4];
static __device__ float    d_emb    [(size_t)E_ * M_ * 4];
static __device__ float    d_logit  [(size_t)E_ * M_];
static __device__ unsigned d_mx     [NN_ * M_];
static __device__ float    d_den    [NN_ * M_];
static __device__ float    d_lenv   [NN_ * M_ * 4];
static __device__ float    d_envnode[NN_ * M_ * 4];
static __device__ float    d_P      [(size_t)NN_ * 1024];
static __device__ float    d_P2     [(size_t)NN_ * 1024];
// k-paired weights, padded +2 rows so prefetch may over-read safely
static __device__ float2   d_W1p  [70 * 256];
static __device__ float2   d_W2p  [130 * 128];
static __device__ float2   d_Wenvp[66 * 160];
static __device__ float2   d_Wq0p [34 * 1024];
static __device__ float2   d_Wq1p [34 * 1024];
static __device__ float2   d_Wqsp [4 * 1024];
// Wk packed 4-k-per-col: d_WkQ[j4*1024 + c] = (Wk[4j4][c],Wk[4j4+1][c],Wk[4j4+2][c],Wk[4j4+3][c])
static __device__ float4   d_WkQ  [32 * 1024];

// ---------------- helpers ----------------
static __device__ __forceinline__ void ffma2(unsigned long long& a,
                                             unsigned long long x,
                                             unsigned long long w) {
    asm("fma.rn.f32x2 %0, %1, %2, %0;" : "+l"(a) : "l"(x), "l"(w));
}
static __device__ __forceinline__ float f2sum(unsigned long long a) {
    return __uint_as_float((unsigned)(a & 0xffffffffu)) +
           __uint_as_float((unsigned)(a >> 32));
}
#define ULD(p) (*(const unsigned long long*)(p))

static __device__ __forceinline__ unsigned encf(float f) {
    unsigned u = __float_as_uint(f);
    return (u & 0x80000000u) ? ~u : (u | 0x80000000u);
}
static __device__ __forceinline__ float decf(unsigned u) {
    return (u & 0x80000000u) ? __uint_as_float(u & 0x7FFFFFFFu) : __uint_as_float(~u);
}
static __device__ __forceinline__ float wsum(float v) {
    #pragma unroll
    for (int o = 16; o; o >>= 1) v += __shfl_xor_sync(0xFFFFFFFFu, v, o);
    return v;
}

// ---------------- kpack: pair weights along K ----------------
__global__ void kpack(const float* __restrict__ W1, const float* __restrict__ W2,
                      const float* __restrict__ Wenv, const float* __restrict__ Wk,
                      const float* __restrict__ Wq) {
    int t = blockIdx.x * blockDim.x + threadIdx.x;
    int S = gridDim.x * blockDim.x;
    for (int i = t; i < 68 * 256; i += S) {
        int j = i >> 8, c = i & 255;
        d_W1p[i] = make_float2(W1[(2*j)*256 + c], W1[(2*j+1)*256 + c]);
    }
    for (int i = t; i < 128 * 128; i += S) {
        int j = i >> 7, c = i & 127;
        d_W2p[i] = make_float2(W2[(2*j)*128 + c], W2[(2*j+1)*128 + c]);
    }
    for (int i = t; i < 64 * 160; i += S) {
        int j = i / 160, c = i - j * 160;
        d_Wenvp[i] = make_float2(Wenv[(2*j)*160 + c], Wenv[(2*j+1)*160 + c]);
    }
    for (int i = t; i < 32 * 1024; i += S) {
        int j4 = i >> 10, c = i & 1023;
        d_WkQ[i] = make_float4(Wk[(size_t)(4*j4+0)*1024 + c],
                               Wk[(size_t)(4*j4+1)*1024 + c],
                               Wk[(size_t)(4*j4+2)*1024 + c],
                               Wk[(size_t)(4*j4+3)*1024 + c]);
    }
    for (int i = t; i < 32 * 1024; i += S) {
        int j = i >> 10, c = i & 1023;
        d_Wq0p[i] = make_float2(Wq[(size_t)(2*j)*1024 + c], Wq[(size_t)(2*j+1)*1024 + c]);
        d_Wq1p[i] = make_float2(Wq[(size_t)(64+2*j)*1024 + c], Wq[(size_t)(64+2*j+1)*1024 + c]);
    }
    for (int i = t; i < 4 * 1024; i += S) {
        int j = i >> 10, c = i & 1023;
        d_Wqsp[i] = make_float2(Wq[(size_t)(128+2*j)*1024 + c], Wq[(size_t)(128+2*j+1)*1024 + c]);
    }
}

// ---------------- kP: node projections P, P2 ----------------
__global__ __launch_bounds__(TPB) void kP(const float* __restrict__ node_inv) {
    __shared__ __align__(16) float sN[TILE][64];
    const int n0 = blockIdx.x * TILE, tid = threadIdx.x;
    for (int idx = tid; idx < TILE * 64; idx += TPB)
        sN[idx >> 6][idx & 63] = node_inv[(size_t)n0 * 64 + idx];
    __syncthreads();
    for (int i = 0; i < 8; i++) {
        const int col = tid + 128 * i;
        unsigned long long a1[TILE], a2[TILE];
        #pragma unroll
        for (int e = 0; e < TILE; e++) { a1[e] = 0ull; a2[e] = 0ull; }
        for (int k = 0; k < 64; k += 4) {
            int j = k >> 1;
            unsigned long long w10 = ULD(&d_Wq0p[j*1024 + col]);
            unsigned long long w11 = ULD(&d_Wq0p[(j+1)*1024 + col]);
            unsigned long long w20 = ULD(&d_Wq1p[j*1024 + col]);
            unsigned long long w21 = ULD(&d_Wq1p[(j+1)*1024 + col]);
            #pragma unroll
            for (int e = 0; e < TILE; e++) {
                ulonglong2 x = *(const ulonglong2*)&sN[e][k];
                ffma2(a1[e], x.x, w10); ffma2(a1[e], x.y, w11);
                ffma2(a2[e], x.x, w20); ffma2(a2[e], x.y, w21);
            }
        }
        #pragma unroll
        for (int e = 0; e < TILE; e++) {
            d_P [(size_t)(n0+e)*1024 + col] = f2sum(a1[e]);
            d_P2[(size_t)(n0+e)*1024 + col] = f2sum(a2[e]);
        }
    }
}

// ---------------- K0: clear node accumulators ----------------
__global__ void k0_init() {
    int i = blockIdx.x * blockDim.x + threadIdx.x;
    if (i < NN_ * M_ * 4) d_lenv[i] = 0.f;
    if (i < NN_ * M_)    { d_mx[i] = 0u; d_den[i] = 0.f; }
}

// ---------------- K1a: LN + MLP + Wenv + eq/emb (banked R13 form) ----------------
__global__ __launch_bounds__(TPB, 5) void k1a(
    const float* __restrict__ inv_cat, const float* __restrict__ cutoff,
    const float* __restrict__ eqf,     const float* __restrict__ eattr,
    const float* __restrict__ lng,     const float* __restrict__ lnb,
    const float* __restrict__ b1,      const float* __restrict__ b2,
    float* __restrict__ out_lat,       float* __restrict__ out_inv)
{
    __shared__ __align__(16) float sX[TILE][140];
    __shared__ __align__(16) float sH[TILE][256];
    __shared__ __align__(16) float sL[TILE][128];
    __shared__ float sW[TILE][160];
    __shared__ float sMu[TILE], sIs[TILE], sCut[TILE];

    const int e0  = blockIdx.x * TILE;
    const int tid = threadIdx.x;
    const int w   = tid >> 5, lane = tid & 31;

    for (int idx = tid; idx < TILE * IN2B_; idx += TPB)
        sX[idx / IN2B_][idx % IN2B_] = inv_cat[(size_t)e0 * IN2B_ + idx];
    if (tid < TILE) sCut[tid] = cutoff[e0 + tid];
    __syncthreads();

    for (int e = w; e < TILE; e += 4) {
        float s = 0.f, q = 0.f;
        for (int k = lane; k < IN2B_; k += 32) { float v = sX[e][k]; s += v; q += v * v; }
        s = wsum(s); q = wsum(q);
        if (lane == 0) {
            float mu = s * (1.f / IN2B_);
            float var = q * (1.f / IN2B_) - mu * mu;
            sMu[e] = mu; sIs[e] = rsqrtf(var + 1e-5f);
        }
    }
    __syncthreads();
    for (int idx = tid; idx < TILE * IN2B_; idx += TPB) {
        int e = idx / IN2B_, k = idx % IN2B_;
        sX[e][k] = (sX[e][k] - sMu[e]) * sIs[e] * lng[k] + lnb[k];
    }
    __syncthreads();

    // GEMM1: 136 -> 256, 1 col/thread, two halves, prefetch
    for (int h = 0; h < 2; h++) {
        const int col = tid + 128 * h;
        unsigned long long acc[TILE];
        #pragma unroll
        for (int e = 0; e < TILE; e++) acc[e] = 0ull;
        unsigned long long w0 = ULD(&d_W1p[col]);
        unsigned long long w1 = ULD(&d_W1p[256 + col]);
        for (int k = 0; k < IN2B_; k += 4) {
            int j = k >> 1;
            unsigned long long nw0 = ULD(&d_W1p[(j+2)*256 + col]);
            unsigned long long nw1 = ULD(&d_W1p[(j+3)*256 + col]);
            #pragma unroll
            for (int e = 0; e < TILE; e++) {
                ulonglong2 x = *(const ulonglong2*)&sX[e][k];
                ffma2(acc[e], x.x, w0); ffma2(acc[e], x.y, w1);
            }
            w0 = nw0; w1 = nw1;
        }
        float bb = b1[col];
        #pragma unroll
        for (int e = 0; e < TILE; e++) {
            float v = f2sum(acc[e]) + bb;
            sH[e][col] = v / (1.f + expf(-v));
        }
    }
    __syncthreads();

    // GEMM2: 256 -> 128
    {
        unsigned long long acc[TILE];
        #pragma unroll
        for (int e = 0; e < TILE; e++) acc[e] = 0ull;
        unsigned long long w0 = ULD(&d_W2p[tid]);
        unsigned long long w1 = ULD(&d_W2p[128 + tid]);
        for (int k = 0; k < HID_; k += 4) {
            int j = k >> 1;
            unsigned long long nw0 = ULD(&d_W2p[(j+2)*128 + tid]);
            unsigned long long nw1 = ULD(&d_W2p[(j+3)*128 + tid]);
            #pragma unroll
            for (int e = 0; e < TILE; e++) {
                ulonglong2 x = *(const ulonglong2*)&sH[e][k];
                ffma2(acc[e], x.x, w0); ffma2(acc[e], x.y, w1);
            }
            w0 = nw0; w1 = nw1;
        }
        float bb = b2[tid];
        #pragma unroll
        for (int e = 0; e < TILE; e++) {
            float v = sCut[e] * (f2sum(acc[e]) + bb);
            sL[e][tid] = v;
            out_lat[(size_t)(e0 + e) * LAT_ + tid] = v;
            out_inv[(size_t)(e0 + e) * 192 + tid]  = v;
        }
    }
    __syncthreads();

    // Wenv pass 0: cols 0..127
    {
        unsigned long long acc[TILE];
        #pragma unroll
        for (int e = 0; e < TILE; e++) acc[e] = 0ull;
        unsigned long long w0 = ULD(&d_Wenvp[tid]);
        unsigned long long w1 = ULD(&d_Wenvp[160 + tid]);
        for (int k = 0; k < LAT_; k += 4) {
            int j = k >> 1;
            unsigned long long nw0 = ULD(&d_Wenvp[(j+2)*160 + tid]);
            unsigned long long nw1 = ULD(&d_Wenvp[(j+3)*160 + tid]);
            #pragma unroll
            for (int e = 0; e < TILE; e++) {
                ulonglong2 x = *(const ulonglong2*)&sL[e][k];
                ffma2(acc[e], x.x, w0); ffma2(acc[e], x.y, w1);
            }
            w0 = nw0; w1 = nw1;
        }
        #pragma unroll
        for (int e = 0; e < TILE; e++) sW[e][tid] = f2sum(acc[e]);
    }
    // Wenv pass 1: cols 128..159
    if (tid < 32) {
        const int col = 128 + tid;
        unsigned long long acc[TILE];
        #pragma unroll
        for (int e = 0; e < TILE; e++) acc[e] = 0ull;
        unsigned long long w0 = ULD(&d_Wenvp[col]);
        unsigned long long w1 = ULD(&d_Wenvp[160 + col]);
        for (int k = 0; k < LAT_; k += 4) {
            int j = k >> 1;
            unsigned long long nw0 = ULD(&d_Wenvp[(j+2)*160 + col]);
            unsigned long long nw1 = ULD(&d_Wenvp[(j+3)*160 + col]);
            #pragma unroll
            for (int e = 0; e < TILE; e++) {
                ulonglong2 x = *(const ulonglong2*)&sL[e][k];
                ffma2(acc[e], x.x, w0); ffma2(acc[e], x.y, w1);
            }
            w0 = nw0; w1 = nw1;
        }
        #pragma unroll
        for (int e = 0; e < TILE; e++) sW[e][col] = f2sum(acc[e]);
    }
    __syncthreads();

    for (int idx = tid; idx < TILE * M_; idx += TPB) {
        int e = idx / M_, m = idx % M_;
        size_t ge = (size_t)(e0 + e) * M_ + m;
        float w0 = sW[e][2*m], w1 = sW[e][2*m+1];
        float q0 = eqf[(size_t)(e0+e)*4+0], q1 = eqf[(size_t)(e0+e)*4+1];
        float q2 = eqf[(size_t)(e0+e)*4+2], q3 = eqf[(size_t)(e0+e)*4+3];
        ((float4*)d_eq)[ge] = make_float4(q0*w0, q1*w1, q2*w1, q3*w1);
        float u0 = sW[e][64+2*m], u1 = sW[e][64+2*m+1];
        float a0 = eattr[(size_t)(e0+e)*4+0], a1 = eattr[(size_t)(e0+e)*4+1];
        float a2 = eattr[(size_t)(e0+e)*4+2], a3 = eattr[(size_t)(e0+e)*4+3];
        ((float4*)d_emb)[ge] = make_float4(a0*u0, a1*u1, a2*u1, a3*u1);
    }
}

// ---------------- K1b: packed-LDS K-GEMM (warp = 16 edges x 1 head) ----------------
// lane = eg*4+cg: edges {eg, eg+8}; cols {h*32 + cg + 4i}, i=0..7
__global__ __launch_bounds__(TPB, 4) void k1b(
    const float* __restrict__ lat, const float* __restrict__ edge_inv,
    const int* __restrict__ ecen,  const int* __restrict__ enei)
{
    __shared__ __align__(16) float sL[TILE][132];   // pad 132 -> conflict-free 8-row LDS.128
    __shared__ __align__(16) float sEI[TILE][8];
    __shared__ int sC[TILE], sN2[TILE];

    const int e0   = blockIdx.x * TILE;
    const int tid  = threadIdx.x;
    const int warp = tid >> 5, lane = tid & 31;
    const int eg   = lane >> 2, cg = lane & 3;
    const int ea   = eg, eb = eg + 8;

    for (int idx = tid; idx < TILE * 128; idx += TPB)
        sL[idx >> 7][idx & 127] = lat[(size_t)e0 * 128 + idx];
    for (int idx = tid; idx < TILE * 8; idx += TPB)
        sEI[idx >> 3][idx & 7] = edge_inv[(size_t)e0 * 8 + idx];
    if (tid < TILE) { sC[tid] = ecen[e0 + tid]; sN2[tid] = enei[e0 + tid]; }
    __syncthreads();

    const int cea = sC[ea], nea = sN2[ea], ceb = sC[eb], neb = sN2[eb];
    unsigned long long eiA[4], eiB[4];
    #pragma unroll
    for (int j = 0; j < 4; j++) { eiA[j] = ULD(&sEI[ea][2*j]); eiB[j] = ULD(&sEI[eb][2*j]); }

    for (int pass = 0; pass < 8; pass++) {
        const int h     = pass * 4 + warp;
        const int cbase = h * 32 + cg;
        unsigned long long acc0[8], acc1[8];
        #pragma unroll
        for (int i = 0; i < 8; i++) { acc0[i] = 0ull; acc1[i] = 0ull; }

        for (int j4 = 0; j4 < 32; j4++) {
            ulonglong2 xa = *(const ulonglong2*)&sL[ea][4*j4];
            ulonglong2 xb = *(const ulonglong2*)&sL[eb][4*j4];
            #pragma unroll
            for (int i = 0; i < 8; i++) {
                ulonglong2 wv = ((const ulonglong2*)d_WkQ)[(size_t)j4*1024 + cbase + 4*i];
                ffma2(acc0[i], xa.x, wv.x); ffma2(acc0[i], xa.y, wv.y);
                ffma2(acc1[i], xb.x, wv.x); ffma2(acc1[i], xb.y, wv.y);
            }
        }

        float p0 = 0.f, p1 = 0.f;
        #pragma unroll
        for (int i = 0; i < 8; i++) {
            const int c = cbase + 4*i;
            unsigned long long qa = 0ull, qb = 0ull;
            #pragma unroll
            for (int j = 0; j < 4; j++) {
                unsigned long long wq = ULD(&d_Wqsp[j*1024 + c]);
                ffma2(qa, eiA[j], wq); ffma2(qb, eiB[j], wq);
            }
            float q0 = f2sum(qa) + d_P[(size_t)cea*1024 + c] + d_P2[(size_t)nea*1024 + c];
            float q1 = f2sum(qb) + d_P[(size_t)ceb*1024 + c] + d_P2[(size_t)neb*1024 + c];
            p0 = fmaf(q0, f2sum(acc0[i]), p0);
            p1 = fmaf(q1, f2sum(acc1[i]), p1);
        }
        p0 += __shfl_xor_sync(0xFFFFFFFFu, p0, 1);
        p0 += __shfl_xor_sync(0xFFFFFFFFu, p0, 2);
        p1 += __shfl_xor_sync(0xFFFFFFFFu, p1, 1);
        p1 += __shfl_xor_sync(0xFFFFFFFFu, p1, 2);

        if (cg == 0) {
            float lg = 5.0f * p0;   // ISQRTD = isqrt(32) = 5
            d_logit[(size_t)(e0 + ea) * M_ + h] = lg;
            atomicMax(&d_mx[(size_t)cea * M_ + h], encf(lg));
        } else if (cg == 1) {
            float lg = 5.0f * p1;
            d_logit[(size_t)(e0 + eb) * M_ + h] = lg;
            atomicMax(&d_mx[(size_t)ceb * M_ + h], encf(lg));
        }
    }
}

// ---------------- K24: fused exp + den-accumulate + weighted segment-sum ----------------
__global__ void k24(const int* __restrict__ ecen) {
    int t = blockIdx.x * blockDim.x + threadIdx.x;
    if (t >= E_ * M_) return;
    int e = t >> 5, m = t & 31;
    int c = ecen[e];
    float mx = decf(d_mx[c * M_ + m]);
    float ex = expf(d_logit[t] - mx);
    atomicAdd(&d_den[c * M_ + m], ex);
    float4 v = ((const float4*)d_emb)[t];
    float* dst = &d_lenv[((size_t)c * M_ + m) * 4];
    atomicAdd(dst + 0, v.x * ex);
    atomicAdd(dst + 1, v.y * ex);
    atomicAdd(dst + 2, v.z * ex);
    atomicAdd(dst + 3, v.w * ex);
}

// ---------------- K5: normalize by den, SO3-LN + W_el0/W_el1 ----------------
__global__ __launch_bounds__(128) void k5_node(
    const float* __restrict__ Wel0, const float* __restrict__ Wel1)
{
    __shared__ float ns[4][33];
    __shared__ float nv[4][3][33];
    int w = threadIdx.x >> 5, lane = threadIdx.x & 31;
    int n = blockIdx.x * 4 + w;
    float4 le = ((const float4*)d_lenv)[(size_t)n * M_ + lane];
    float den = d_den[(size_t)n * M_ + lane];
    float inv = (den > 0.f) ? (1.f / den) : 0.f;
    le.x *= inv; le.y *= inv; le.z *= inv; le.w *= inv;
    float rms_s = sqrtf(wsum(le.x * le.x) * (1.f / 32.f) + 1e-5f);
    float rms_v = sqrtf(wsum(le.y*le.y + le.z*le.z + le.w*le.w) * (1.f / 96.f) + 1e-5f);
    ns[w][lane]    = le.x / rms_s;
    nv[w][0][lane] = le.y / rms_v;
    nv[w][1][lane] = le.z / rms_v;
    nv[w][2][lane] = le.w / rms_v;
    __syncwarp();
    float ls = 0.f, l0 = 0.f, l1 = 0.f, l2 = 0.f;
    #pragma unroll
    for (int u = 0; u < 32; u++) {
        float w0 = Wel0[u * 32 + lane];
        float w1 = Wel1[u * 32 + lane];
        ls += ns[w][u] * w0;
        l0 += nv[w][0][u] * w1;
        l1 += nv[w][1][u] * w1;
        l2 += nv[w][2][u] * w1;
    }
    ((float4*)d_envnode)[(size_t)n * M_ + lane] = make_float4(ls, l0, l1, l2);
}

// ---------------- K6: CG tensor product + SO3-LN + output linears ----------------
__global__ __launch_bounds__(128) void k6_tp(
    const int*   __restrict__ ecen,
    const float* __restrict__ Wls, const float* __restrict__ Wlv,
    float* __restrict__ out_inv, float* __restrict__ out_eq)
{
    __shared__ float tp[4][M_][12];
    const int w = threadIdx.x >> 5, lane = threadIdx.x & 31;
    const int e = blockIdx.x * 4 + w;
    const float INV_SQ3 = 0.57735026918962576f;
    const float INV_SQ2 = 0.70710678118654752f;

    float4 xq = ((const float4*)d_eq)[(size_t)e * M_ + lane];
    int c = ecen[e];
    float4 ye = ((const float4*)d_envnode)[(size_t)c * M_ + lane];
    float x0 = xq.x, xa = xq.y, xb = xq.z, xc = xq.w;
    float y0 = ye.x, ya = ye.y, yb = ye.z, yc = ye.w;

    float t0 = x0 * y0;
    float t1 = (xa*ya + xb*yb + xc*yc) * INV_SQ3;
    float t2 = x0*ya, t3 = x0*yb, t4 = x0*yc;
    float t5 = xa*y0, t6 = xb*y0, t7 = xc*y0;
    float t8  = (xb*yc - xc*yb) * INV_SQ2;
    float t9  = (xc*ya - xa*yc) * INV_SQ2;
    float t10 = (xa*yb - xb*ya) * INV_SQ2;

    float r0 = sqrtf(wsum(t0*t0) * (1.f/32.f) + 1e-5f);
    float r1 = sqrtf(wsum(t1*t1) * (1.f/32.f) + 1e-5f);
    float r2 = sqrtf(wsum(t2*t2 + t3*t3 + t4*t4) * (1.f/96.f) + 1e-5f);
    float r3 = sqrtf(wsum(t5*t5 + t6*t6 + t7*t7) * (1.f/96.f) + 1e-5f);
    float r4 = sqrtf(wsum(t8*t8 + t9*t9 + t10*t10) * (1.f/96.f) + 1e-5f);

    tp[w][lane][0]  = t0 / r0;  tp[w][lane][1] = t1 / r1;
    tp[w][lane][2]  = t2 / r2;  tp[w][lane][3] = t3 / r2;  tp[w][lane][4]  = t4 / r2;
    tp[w][lane][5]  = t5 / r3;  tp[w][lane][6] = t6 / r3;  tp[w][lane][7]  = t7 / r3;
    tp[w][lane][8]  = t8 / r4;  tp[w][lane][9] = t9 / r4;  tp[w][lane][10] = t10 / r4;
    __syncwarp();

    out_inv[(size_t)e * 192 + 128 + lane] = tp[w][lane >> 1][lane & 1];
    out_inv[(size_t)e * 192 + 160 + lane] = tp[w][(lane + 32) >> 1][lane & 1];

    float os = 0.f, ov0 = 0.f, ov1 = 0.f, ov2 = 0.f;
    #pragma unroll
    for (int u = 0; u < 32; u++) {
        os += tp[w][u][0] * Wls[u * 32 + lane];
        os += tp[w][u][1] * Wls[(32 + u) * 32 + lane];
        float wv0 = Wlv[u * 32 + lane];
        float wv1 = Wlv[(32 + u) * 32 + lane];
        float wv2 = Wlv[(64 + u) * 32 + lane];
        ov0 += tp[w][u][2]*wv0 + tp[w][u][5]*wv1 + tp[w][u][8]*wv2;
        ov1 += tp[w][u][3]*wv0 + tp[w][u][6]*wv1 + tp[w][u][9]*wv2;
        ov2 += tp[w][u][4]*wv0 + tp[w][u][7]*wv1 + tp[w][u][10]*wv2;
    }
    ((float4*)out_eq)[(size_t)e * M_ + lane] = make_float4(os, ov0, ov1, ov2);
}

// ---------------- launch ----------------
extern "C" void kernel_launch(void* const* d_in, const int* in_sizes, int n_in,
                              void* d_out, int out_size) {
    const float* inv_cat  = (const float*)d_in[1];
    const float* eqf      = (const float*)d_in[2];
    const float* cutoff   = (const float*)d_in[3];
    const float* eattr    = (const float*)d_in[4];
    const float* node_inv = (const float*)d_in[5];
    const float* edge_inv = (const float*)d_in[6];
    const float* lng      = (const float*)d_in[7];
    const float* lnb      = (const float*)d_in[8];
    const float* W1       = (const float*)d_in[9];
    const float* b1       = (const float*)d_in[10];
    const float* W2       = (const float*)d_in[11];
    const float* b2       = (const float*)d_in[12];
    const float* Wenv     = (const float*)d_in[13];
    const float* Wq       = (const float*)d_in[14];
    const float* Wk       = (const float*)d_in[15];
    const float* Wel0     = (const float*)d_in[16];
    const float* Wel1     = (const float*)d_in[17];
    const float* Wls      = (const float*)d_in[18];
    const float* Wlv      = (const float*)d_in[19];
    const int*   ecen     = (const int*)d_in[20];
    const int*   enei     = (const int*)d_in[21];

    float* out      = (float*)d_out;
    float* out_lat  = out;
    float* out_inv  = out + (size_t)E_ * 128;
    float* out_eq   = out + (size_t)E_ * (128 + 192);

    kpack<<<512, 256>>>(W1, W2, Wenv, Wk, Wq);
    k0_init<<<(NN_ * M_ * 4 + 255) / 256, 256>>>();
    kP<<<NN_ / TILE, TPB>>>(node_inv);
    k1a<<<E_ / TILE, TPB>>>(inv_cat, cutoff, eqf, eattr,
                            lng, lnb, b1, b2, out_lat, out_inv);
    k1b<<<E_ / TILE, TPB>>>(out_lat, edge_inv, ecen, enei);
    k24<<<(E_ * M_) / 256, 256>>>(ecen);
    k5_node<<<NN_ / 4, 128>>>(Wel0, Wel1);
    k6_tp<<<E_ / 4, 128>>>(ecen, Wls, Wlv, out_inv, out_eq);
}

// round 17
// speedup vs baseline: 1.3878x; 1.3878x over previous
#include <cuda_runtime.h>
#include <math.h>

#define E_    256000
#define NN_   16000
#define M_    32
#define LAT_  128
#define IN2B_ 136
#define HID_  256
#define GENW_ 160
#define TILE  16
#define TPB   128

// ---------------- scratch (static device globals; no allocation) ----------------
static __device__ float    d_eq     [(size_t)E_ * M_ * 4];
static __device__ float    d_emb    [(size_t)E_ * M_ * 4];
static __device__ float    d_logit  [(size_t)E_ * M_];
static __device__ unsigned d_mx     [NN_ * M_];
static __device__ float    d_den    [NN_ * M_];
static __device__ float    d_lenv   [NN_ * M_ * 4];
static __device__ float    d_envnode[NN_ * M_ * 4];
static __device__ float    d_P      [(size_t)NN_ * 1024];
static __device__ float    d_P2     [(size_t)NN_ * 1024];
// k-paired weights, padded +2 rows so prefetch may over-read safely
static __device__ float2   d_W1p  [70 * 256];
static __device__ float2   d_W2p  [130 * 128];
static __device__ float2   d_Wenvp[66 * 160];
static __device__ float2   d_Wkp  [66 * 1024];
static __device__ float2   d_Wq0p [34 * 1024];
static __device__ float2   d_Wq1p [34 * 1024];
static __device__ float2   d_Wqsp [4 * 1024];

// ---------------- helpers ----------------
static __device__ __forceinline__ void ffma2(unsigned long long& a,
                                             unsigned long long x,
                                             unsigned long long w) {
    asm("fma.rn.f32x2 %0, %1, %2, %0;" : "+l"(a) : "l"(x), "l"(w));
}
static __device__ __forceinline__ float f2sum(unsigned long long a) {
    return __uint_as_float((unsigned)(a & 0xffffffffu)) +
           __uint_as_float((unsigned)(a >> 32));
}
#define ULD(p) (*(const unsigned long long*)(p))

static __device__ __forceinline__ unsigned encf(float f) {
    unsigned u = __float_as_uint(f);
    return (u & 0x80000000u) ? ~u : (u | 0x80000000u);
}
static __device__ __forceinline__ float decf(unsigned u) {
    return (u & 0x80000000u) ? __uint_as_float(u & 0x7FFFFFFFu) : __uint_as_float(~u);
}
static __device__ __forceinline__ float wsum(float v) {
    #pragma unroll
    for (int o = 16; o; o >>= 1) v += __shfl_xor_sync(0xFFFFFFFFu, v, o);
    return v;
}
// joint reduction of two values: lanes 0..15 hold sum(v0), lanes 16..31 hold sum(v1)
static __device__ __forceinline__ float wsum2(float v0, float v1, int lane) {
    float p0 = v0 + __shfl_xor_sync(0xFFFFFFFFu, v0, 16);
    float p1 = v1 + __shfl_xor_sync(0xFFFFFFFFu, v1, 16);
    float x = (lane < 16) ? p0 : p1;
    #pragma unroll
    for (int o = 8; o; o >>= 1) x += __shfl_xor_sync(0xFFFFFFFFu, x, o);
    return x;
}

// ---------------- kpack: pair weights along K ----------------
__global__ void kpack(const float* __restrict__ W1, const float* __restrict__ W2,
                      const float* __restrict__ Wenv, const float* __restrict__ Wk,
                      const float* __restrict__ Wq) {
    int t = blockIdx.x * blockDim.x + threadIdx.x;
    int S = gridDim.x * blockDim.x;
    for (int i = t; i < 68 * 256; i += S) {
        int j = i >> 8, c = i & 255;
        d_W1p[i] = make_float2(W1[(2*j)*256 + c], W1[(2*j+1)*256 + c]);
    }
    for (int i = t; i < 128 * 128; i += S) {
        int j = i >> 7, c = i & 127;
        d_W2p[i] = make_float2(W2[(2*j)*128 + c], W2[(2*j+1)*128 + c]);
    }
    for (int i = t; i < 64 * 160; i += S) {
        int j = i / 160, c = i - j * 160;
        d_Wenvp[i] = make_float2(Wenv[(2*j)*160 + c], Wenv[(2*j+1)*160 + c]);
    }
    for (int i = t; i < 64 * 1024; i += S) {
        int j = i >> 10, c = i & 1023;
        d_Wkp[i] = make_float2(Wk[(size_t)(2*j)*1024 + c], Wk[(size_t)(2*j+1)*1024 + c]);
    }
    for (int i = t; i < 32 * 1024; i += S) {
        int j = i >> 10, c = i & 1023;
        d_Wq0p[i] = make_float2(Wq[(size_t)(2*j)*1024 + c], Wq[(size_t)(2*j+1)*1024 + c]);
        d_Wq1p[i] = make_float2(Wq[(size_t)(64+2*j)*1024 + c], Wq[(size_t)(64+2*j+1)*1024 + c]);
    }
    for (int i = t; i < 4 * 1024; i += S) {
        int j = i >> 10, c = i & 1023;
        d_Wqsp[i] = make_float2(Wq[(size_t)(128+2*j)*1024 + c], Wq[(size_t)(128+2*j+1)*1024 + c]);
    }
}

// ---------------- kP: node projections P, P2 ----------------
__global__ __launch_bounds__(TPB) void kP(const float* __restrict__ node_inv) {
    __shared__ __align__(16) float sN[TILE][64];
    const int n0 = blockIdx.x * TILE, tid = threadIdx.x;
    for (int idx = tid; idx < TILE * 64; idx += TPB)
        sN[idx >> 6][idx & 63] = node_inv[(size_t)n0 * 64 + idx];
    __syncthreads();
    for (int i = 0; i < 8; i++) {
        const int col = tid + 128 * i;
        unsigned long long a1[TILE], a2[TILE];
        #pragma unroll
        for (int e = 0; e < TILE; e++) { a1[e] = 0ull; a2[e] = 0ull; }
        for (int k = 0; k < 64; k += 4) {
            int j = k >> 1;
            unsigned long long w10 = ULD(&d_Wq0p[j*1024 + col]);
            unsigned long long w11 = ULD(&d_Wq0p[(j+1)*1024 + col]);
            unsigned long long w20 = ULD(&d_Wq1p[j*1024 + col]);
            unsigned long long w21 = ULD(&d_Wq1p[(j+1)*1024 + col]);
            #pragma unroll
            for (int e = 0; e < TILE; e++) {
                ulonglong2 x = *(const ulonglong2*)&sN[e][k];
                ffma2(a1[e], x.x, w10); ffma2(a1[e], x.y, w11);
                ffma2(a2[e], x.x, w20); ffma2(a2[e], x.y, w21);
            }
        }
        #pragma unroll
        for (int e = 0; e < TILE; e++) {
            d_P [(size_t)(n0+e)*1024 + col] = f2sum(a1[e]);
            d_P2[(size_t)(n0+e)*1024 + col] = f2sum(a2[e]);
        }
    }
}

// ---------------- K0: clear node accumulators ----------------
__global__ void k0_init() {
    int i = blockIdx.x * blockDim.x + threadIdx.x;
    if (i < NN_ * M_ * 4) d_lenv[i] = 0.f;
    if (i < NN_ * M_)    { d_mx[i] = 0u; d_den[i] = 0.f; }
}

// ---------------- K1a: LN + MLP + Wenv + eq/emb (smem diet: sW aliases sH; occ 6) ----------------
__global__ __launch_bounds__(TPB, 6) void k1a(
    const float* __restrict__ inv_cat, const float* __restrict__ cutoff,
    const float* __restrict__ eqf,     const float* __restrict__ eattr,
    const float* __restrict__ lng,     const float* __restrict__ lnb,
    const float* __restrict__ b1,      const float* __restrict__ b2,
    float* __restrict__ out_lat,       float* __restrict__ out_inv)
{
    __shared__ __align__(16) float sX[TILE][140];
    __shared__ __align__(16) float sH[TILE][256];   // aliased by sW after GEMM2
    __shared__ __align__(16) float sL[TILE][128];
    __shared__ float sMu[TILE], sIs[TILE], sCut[TILE];
    float* sWf = &sH[0][0];                          // sW[e][c] = sWf[e*160 + c]

    const int e0  = blockIdx.x * TILE;
    const int tid = threadIdx.x;
    const int w   = tid >> 5, lane = tid & 31;

    for (int idx = tid; idx < TILE * IN2B_; idx += TPB)
        sX[idx / IN2B_][idx % IN2B_] = inv_cat[(size_t)e0 * IN2B_ + idx];
    if (tid < TILE) sCut[tid] = cutoff[e0 + tid];
    __syncthreads();

    for (int e = w; e < TILE; e += 4) {
        float s = 0.f, q = 0.f;
        for (int k = lane; k < IN2B_; k += 32) { float v = sX[e][k]; s += v; q += v * v; }
        s = wsum(s); q = wsum(q);
        if (lane == 0) {
            float mu = s * (1.f / IN2B_);
            float var = q * (1.f / IN2B_) - mu * mu;
            sMu[e] = mu; sIs[e] = rsqrtf(var + 1e-5f);
        }
    }
    __syncthreads();
    for (int idx = tid; idx < TILE * IN2B_; idx += TPB) {
        int e = idx / IN2B_, k = idx % IN2B_;
        sX[e][k] = (sX[e][k] - sMu[e]) * sIs[e] * lng[k] + lnb[k];
    }
    __syncthreads();

    // GEMM1: 136 -> 256, 1 col/thread, two halves, prefetch
    for (int h = 0; h < 2; h++) {
        const int col = tid + 128 * h;
        unsigned long long acc[TILE];
        #pragma unroll
        for (int e = 0; e < TILE; e++) acc[e] = 0ull;
        unsigned long long w0 = ULD(&d_W1p[col]);
        unsigned long long w1 = ULD(&d_W1p[256 + col]);
        for (int k = 0; k < IN2B_; k += 4) {
            int j = k >> 1;
            unsigned long long nw0 = ULD(&d_W1p[(j+2)*256 + col]);
            unsigned long long nw1 = ULD(&d_W1p[(j+3)*256 + col]);
            #pragma unroll
            for (int e = 0; e < TILE; e++) {
                ulonglong2 x = *(const ulonglong2*)&sX[e][k];
                ffma2(acc[e], x.x, w0); ffma2(acc[e], x.y, w1);
            }
            w0 = nw0; w1 = nw1;
        }
        float bb = b1[col];
        #pragma unroll
        for (int e = 0; e < TILE; e++) {
            float v = f2sum(acc[e]) + bb;
            sH[e][col] = v / (1.f + expf(-v));
        }
    }
    __syncthreads();

    // GEMM2: 256 -> 128
    {
        unsigned long long acc[TILE];
        #pragma unroll
        for (int e = 0; e < TILE; e++) acc[e] = 0ull;
        unsigned long long w0 = ULD(&d_W2p[tid]);
        unsigned long long w1 = ULD(&d_W2p[128 + tid]);
        for (int k = 0; k < HID_; k += 4) {
            int j = k >> 1;
            unsigned long long nw0 = ULD(&d_W2p[(j+2)*128 + tid]);
            unsigned long long nw1 = ULD(&d_W2p[(j+3)*128 + tid]);
            #pragma unroll
            for (int e = 0; e < TILE; e++) {
                ulonglong2 x = *(const ulonglong2*)&sH[e][k];
                ffma2(acc[e], x.x, w0); ffma2(acc[e], x.y, w1);
            }
            w0 = nw0; w1 = nw1;
        }
        float bb = b2[tid];
        #pragma unroll
        for (int e = 0; e < TILE; e++) {
            float v = sCut[e] * (f2sum(acc[e]) + bb);
            sL[e][tid] = v;
            out_lat[(size_t)(e0 + e) * LAT_ + tid] = v;
            out_inv[(size_t)(e0 + e) * 192 + tid]  = v;
        }
    }
    __syncthreads();   // last read of sH above; sW (alias) written below

    // Wenv pass 0: cols 0..127
    {
        unsigned long long acc[TILE];
        #pragma unroll
        for (int e = 0; e < TILE; e++) acc[e] = 0ull;
        unsigned long long w0 = ULD(&d_Wenvp[tid]);
        unsigned long long w1 = ULD(&d_Wenvp[160 + tid]);
        for (int k = 0; k < LAT_; k += 4) {
            int j = k >> 1;
            unsigned long long nw0 = ULD(&d_Wenvp[(j+2)*160 + tid]);
            unsigned long long nw1 = ULD(&d_Wenvp[(j+3)*160 + tid]);
            #pragma unroll
            for (int e = 0; e < TILE; e++) {
                ulonglong2 x = *(const ulonglong2*)&sL[e][k];
                ffma2(acc[e], x.x, w0); ffma2(acc[e], x.y, w1);
            }
            w0 = nw0; w1 = nw1;
        }
        #pragma unroll
        for (int e = 0; e < TILE; e++) sWf[e * 160 + tid] = f2sum(acc[e]);
    }
    // Wenv pass 1: cols 128..159
    if (tid < 32) {
        const int col = 128 + tid;
        unsigned long long acc[TILE];
        #pragma unroll
        for (int e = 0; e < TILE; e++) acc[e] = 0ull;
        unsigned long long w0 = ULD(&d_Wenvp[col]);
        unsigned long long w1 = ULD(&d_Wenvp[160 + col]);
        for (int k = 0; k < LAT_; k += 4) {
            int j = k >> 1;
            unsigned long long nw0 = ULD(&d_Wenvp[(j+2)*160 + col]);
            unsigned long long nw1 = ULD(&d_Wenvp[(j+3)*160 + col]);
            #pragma unroll
            for (int e = 0; e < TILE; e++) {
                ulonglong2 x = *(const ulonglong2*)&sL[e][k];
                ffma2(acc[e], x.x, w0); ffma2(acc[e], x.y, w1);
            }
            w0 = nw0; w1 = nw1;
        }
        #pragma unroll
        for (int e = 0; e < TILE; e++) sWf[e * 160 + col] = f2sum(acc[e]);
    }
    __syncthreads();

    for (int idx = tid; idx < TILE * M_; idx += TPB) {
        int e = idx / M_, m = idx % M_;
        size_t ge = (size_t)(e0 + e) * M_ + m;
        float w0 = sWf[e*160 + 2*m], w1 = sWf[e*160 + 2*m+1];
        float q0 = eqf[(size_t)(e0+e)*4+0], q1 = eqf[(size_t)(e0+e)*4+1];
        float q2 = eqf[(size_t)(e0+e)*4+2], q3 = eqf[(size_t)(e0+e)*4+3];
        ((float4*)d_eq)[ge] = make_float4(q0*w0, q1*w1, q2*w1, q3*w1);
        float u0 = sWf[e*160 + 64+2*m], u1 = sWf[e*160 + 64+2*m+1];
        float a0 = eattr[(size_t)(e0+e)*4+0], a1 = eattr[(size_t)(e0+e)*4+1];
        float a2 = eattr[(size_t)(e0+e)*4+2], a3 = eattr[(size_t)(e0+e)*4+3];
        ((float4*)d_emb)[ge] = make_float4(a0*u0, a1*u1, a2*u1, a3*u1);
    }
}

// ---------------- K1b: K-GEMM (2 cols/thread) + Q assembly + logits (R7 form) ----------------
__global__ __launch_bounds__(TPB, 4) void k1b(
    const float* __restrict__ lat, const float* __restrict__ edge_inv,
    const int* __restrict__ ecen,  const int* __restrict__ enei)
{
    __shared__ __align__(16) float sL[TILE][128];
    __shared__ __align__(16) float sEI[TILE][8];
    __shared__ int sC[TILE], sN2[TILE];

    const int e0  = blockIdx.x * TILE;
    const int tid = threadIdx.x;
    const int w   = tid >> 5, lane = tid & 31;

    for (int idx = tid; idx < TILE * 128; idx += TPB)
        sL[idx >> 7][idx & 127] = lat[(size_t)e0 * 128 + idx];
    for (int idx = tid; idx < TILE * 8; idx += TPB)
        sEI[idx >> 3][idx & 7] = edge_inv[(size_t)e0 * 8 + idx];
    if (tid < TILE) { sC[tid] = ecen[e0 + tid]; sN2[tid] = enei[e0 + tid]; }
    __syncthreads();

    for (int i = 0; i < 4; i++) {
        const int c0 = tid + 128 * i;   // m0 = w + 4*i
        const int c1 = c0 + 512;        // m1 = m0 + 16
        unsigned long long a0[TILE], a1[TILE];
        #pragma unroll
        for (int e = 0; e < TILE; e++) { a0[e] = 0ull; a1[e] = 0ull; }

        const float2* p0 = &d_Wkp[c0];
        const float2* p1 = &d_Wkp[c1];
        unsigned long long w00 = ULD(p0), w01 = ULD(p0 + 1024);
        unsigned long long w10 = ULD(p1), w11 = ULD(p1 + 1024);
        for (int k = 0; k < LAT_; k += 4) {
            p0 += 2048; p1 += 2048;
            unsigned long long n00 = ULD(p0), n01 = ULD(p0 + 1024);
            unsigned long long n10 = ULD(p1), n11 = ULD(p1 + 1024);
            #pragma unroll
            for (int e = 0; e < TILE; e++) {
                ulonglong2 x = *(const ulonglong2*)&sL[e][k];
                ffma2(a0[e], x.x, w00); ffma2(a0[e], x.y, w01);
                ffma2(a1[e], x.x, w10); ffma2(a1[e], x.y, w11);
            }
            w00 = n00; w01 = n01; w10 = n10; w11 = n11;
        }

        unsigned long long qw00 = ULD(&d_Wqsp[c0]),        qw01 = ULD(&d_Wqsp[1024 + c0]);
        unsigned long long qw02 = ULD(&d_Wqsp[2048 + c0]), qw03 = ULD(&d_Wqsp[3072 + c0]);
        unsigned long long qw10 = ULD(&d_Wqsp[c1]),        qw11 = ULD(&d_Wqsp[1024 + c1]);
        unsigned long long qw12 = ULD(&d_Wqsp[2048 + c1]), qw13 = ULD(&d_Wqsp[3072 + c1]);

        float mine0 = 0.f, mine1 = 0.f;
        #pragma unroll
        for (int e = 0; e < TILE; e++) {
            ulonglong2 ei0 = *(const ulonglong2*)&sEI[e][0];
            ulonglong2 ei1 = *(const ulonglong2*)&sEI[e][4];
            unsigned long long qa = 0ull, qb = 0ull;
            ffma2(qa, ei0.x, qw00); ffma2(qa, ei0.y, qw01);
            ffma2(qa, ei1.x, qw02); ffma2(qa, ei1.y, qw03);
            ffma2(qb, ei0.x, qw10); ffma2(qb, ei0.y, qw11);
            ffma2(qb, ei1.x, qw12); ffma2(qb, ei1.y, qw13);
            size_t rc = (size_t)sC[e] * 1024, rn = (size_t)sN2[e] * 1024;
            float q0 = f2sum(qa) + d_P[rc + c0] + d_P2[rn + c0];
            float q1 = f2sum(qb) + d_P[rc + c1] + d_P2[rn + c1];
            float x = wsum2(q0 * f2sum(a0[e]), q1 * f2sum(a1[e]), lane);
            if (lane == e)      mine0 = x;
            if (lane == e + 16) mine1 = x;
        }
        if (lane < TILE) {
            int m0 = w + 4 * i;
            float lg0 = 5.0f * mine0;   // ISQRTD = isqrt(32) = 5
            d_logit[(size_t)(e0 + lane) * M_ + m0] = lg0;
            atomicMax(&d_mx[(size_t)sC[lane] * M_ + m0], encf(lg0));
        } else {
            int le = lane - 16;
            int m1 = w + 4 * i + 16;
            float lg1 = 5.0f * mine1;
            d_logit[(size_t)(e0 + le) * M_ + m1] = lg1;
            atomicMax(&d_mx[(size_t)sC[le] * M_ + m1], encf(lg1));
        }
    }
}

// ---------------- K24: fused exp + den-accumulate + weighted segment-sum ----------------
__global__ void k24(const int* __restrict__ ecen) {
    int t = blockIdx.x * blockDim.x + threadIdx.x;
    if (t >= E_ * M_) return;
    int e = t >> 5, m = t & 31;
    int c = ecen[e];
    float mx = decf(d_mx[c * M_ + m]);
    float ex = expf(d_logit[t] - mx);
    atomicAdd(&d_den[c * M_ + m], ex);
    float4 v = ((const float4*)d_emb)[t];
    float* dst = &d_lenv[((size_t)c * M_ + m) * 4];
    atomicAdd(dst + 0, v.x * ex);
    atomicAdd(dst + 1, v.y * ex);
    atomicAdd(dst + 2, v.z * ex);
    atomicAdd(dst + 3, v.w * ex);
}

// ---------------- K5: normalize by den, SO3-LN + W_el0/W_el1 ----------------
__global__ __launch_bounds__(128) void k5_node(
    const float* __restrict__ Wel0, const float* __restrict__ Wel1)
{
    __shared__ float ns[4][33];
    __shared__ float nv[4][3][33];
    int w = threadIdx.x >> 5, lane = threadIdx.x & 31;
    int n = blockIdx.x * 4 + w;
    float4 le = ((const float4*)d_lenv)[(size_t)n * M_ + lane];
    float den = d_den[(size_t)n * M_ + lane];
    float inv = (den > 0.f) ? (1.f / den) : 0.f;
    le.x *= inv; le.y *= inv; le.z *= inv; le.w *= inv;
    float rms_s = sqrtf(wsum(le.x * le.x) * (1.f / 32.f) + 1e-5f);
    float rms_v = sqrtf(wsum(le.y*le.y + le.z*le.z + le.w*le.w) * (1.f / 96.f) + 1e-5f);
    ns[w][lane]    = le.x / rms_s;
    nv[w][0][lane] = le.y / rms_v;
    nv[w][1][lane] = le.z / rms_v;
    nv[w][2][lane] = le.w / rms_v;
    __syncwarp();
    float ls = 0.f, l0 = 0.f, l1 = 0.f, l2 = 0.f;
    #pragma unroll
    for (int u = 0; u < 32; u++) {
        float w0 = Wel0[u * 32 + lane];
        float w1 = Wel1[u * 32 + lane];
        ls += ns[w][u] * w0;
        l0 += nv[w][0][u] * w1;
        l1 += nv[w][1][u] * w1;
        l2 += nv[w][2][u] * w1;
    }
    ((float4*)d_envnode)[(size_t)n * M_ + lane] = make_float4(ls, l0, l1, l2);
}

// ---------------- K6: CG tensor product + SO3-LN + output linears ----------------
__global__ __launch_bounds__(128) void k6_tp(
    const int*   __restrict__ ecen,
    const float* __restrict__ Wls, const float* __restrict__ Wlv,
    float* __restrict__ out_inv, float* __restrict__ out_eq)
{
    __shared__ float tp[4][M_][12];
    const int w = threadIdx.x >> 5, lane = threadIdx.x & 31;
    const int e = blockIdx.x * 4 + w;
    const float INV_SQ3 = 0.57735026918962576f;
    const float INV_SQ2 = 0.70710678118654752f;

    float4 xq = ((const float4*)d_eq)[(size_t)e * M_ + lane];
    int c = ecen[e];
    float4 ye = ((const float4*)d_envnode)[(size_t)c * M_ + lane];
    float x0 = xq.x, xa = xq.y, xb = xq.z, xc = xq.w;
    float y0 = ye.x, ya = ye.y, yb = ye.z, yc = ye.w;

    float t0 = x0 * y0;
    float t1 = (xa*ya + xb*yb + xc*yc) * INV_SQ3;
    float t2 = x0*ya, t3 = x0*yb, t4 = x0*yc;
    float t5 = xa*y0, t6 = xb*y0, t7 = xc*y0;
    float t8  = (xb*yc - xc*yb) * INV_SQ2;
    float t9  = (xc*ya - xa*yc) * INV_SQ2;
    float t10 = (xa*yb - xb*ya) * INV_SQ2;

    float r0 = sqrtf(wsum(t0*t0) * (1.f/32.f) + 1e-5f);
    float r1 = sqrtf(wsum(t1*t1) * (1.f/32.f) + 1e-5f);
    float r2 = sqrtf(wsum(t2*t2 + t3*t3 + t4*t4) * (1.f/96.f) + 1e-5f);
    float r3 = sqrtf(wsum(t5*t5 + t6*t6 + t7*t7) * (1.f/96.f) + 1e-5f);
    float r4 = sqrtf(wsum(t8*t8 + t9*t9 + t10*t10) * (1.f/96.f) + 1e-5f);

    tp[w][lane][0]  = t0 / r0;  tp[w][lane][1] = t1 / r1;
    tp[w][lane][2]  = t2 / r2;  tp[w][lane][3] = t3 / r2;  tp[w][lane][4]  = t4 / r2;
    tp[w][lane][5]  = t5 / r3;  tp[w][lane][6] = t6 / r3;  tp[w][lane][7]  = t7 / r3;
    tp[w][lane][8]  = t8 / r4;  tp[w][lane][9] = t9 / r4;  tp[w][lane][10] = t10 / r4;
    __syncwarp();

    out_inv[(size_t)e * 192 + 128 + lane] = tp[w][lane >> 1][lane & 1];
    out_inv[(size_t)e * 192 + 160 + lane] = tp[w][(lane + 32) >> 1][lane & 1];

    float os = 0.f, ov0 = 0.f, ov1 = 0.f, ov2 = 0.f;
    #pragma unroll
    for (int u = 0; u < 32; u++) {
        os += tp[w][u][0] * Wls[u * 32 + lane];
        os += tp[w][u][1] * Wls[(32 + u) * 32 + lane];
        float wv0 = Wlv[u * 32 + lane];
        float wv1 = Wlv[(32 + u) * 32 + lane];
        float wv2 = Wlv[(64 + u) * 32 + lane];
        ov0 += tp[w][u][2]*wv0 + tp[w][u][5]*wv1 + tp[w][u][8]*wv2;
        ov1 += tp[w][u][3]*wv0 + tp[w][u][6]*wv1 + tp[w][u][9]*wv2;
        ov2 += tp[w][u][4]*wv0 + tp[w][u][7]*wv1 + tp[w][u][10]*wv2;
    }
    ((float4*)out_eq)[(size_t)e * M_ + lane] = make_float4(os, ov0, ov1, ov2);
}

// ---------------- launch ----------------
extern "C" void kernel_launch(void* const* d_in, const int* in_sizes, int n_in,
                              void* d_out, int out_size) {
    const float* inv_cat  = (const float*)d_in[1];
    const float* eqf      = (const float*)d_in[2];
    const float* cutoff   = (const float*)d_in[3];
    const float* eattr    = (const float*)d_in[4];
    const float* node_inv = (const float*)d_in[5];
    const float* edge_inv = (const float*)d_in[6];
    const float* lng      = (const float*)d_in[7];
    const float* lnb      = (const float*)d_in[8];
    const float* W1       = (const float*)d_in[9];
    const float* b1       = (const float*)d_in[10];
    const float* W2       = (const float*)d_in[11];
    const float* b2       = (const float*)d_in[12];
    const float* Wenv     = (const float*)d_in[13];
    const float* Wq       = (const float*)d_in[14];
    const float* Wk       = (const float*)d_in[15];
    const float* Wel0     = (const float*)d_in[16];
    const float* Wel1     = (const float*)d_in[17];
    const float* Wls      = (const float*)d_in[18];
    const float* Wlv      = (const float*)d_in[19];
    const int*   ecen     = (const int*)d_in[20];
    const int*   enei     = (const int*)d_in[21];

    float* out      = (float*)d_out;
    float* out_lat  = out;
    float* out_inv  = out + (size_t)E_ * 128;
    float* out_eq   = out + (size_t)E_ * (128 + 192);

    kpack<<<512, 256>>>(W1, W2, Wenv, Wk, Wq);
    k0_init<<<(NN_ * M_ * 4 + 255) / 256, 256>>>();
    kP<<<NN_ / TILE, TPB>>>(node_inv);
    k1a<<<E_ / TILE, TPB>>>(inv_cat, cutoff, eqf, eattr,
                            lng, lnb, b1, b2, out_lat, out_inv);
    k1b<<<E_ / TILE, TPB>>>(out_lat, edge_inv, ecen, enei);
    k24<<<(E_ * M_) / 256, 256>>>(ecen);
    k5_node<<<NN_ / 4, 128>>>(Wel0, Wel1);
    k6_tp<<<E_ / 4, 128>>>(ecen, Wls, Wlv, out_inv, out_eq);
}